// round 15
// baseline (speedup 1.0000x reference)
#include <cuda_runtime.h>
#include <cuda_fp16.h>
#include <cuda_bf16.h>
#include <cstdint>

#define DK 128
#define NCTAS 148

// -------- device-global scratch --------
__device__ __align__(128) __half g_ABh[100000 * 256]; // fp16 [node][ A'(=A+b1) | B ]

__device__ __forceinline__ uint32_t smem_u32(const void* p) {
    uint32_t a; asm("{ .reg .u64 t; cvta.to.shared.u64 t, %1; cvt.u32.u64 %0, t; }" : "=r"(a) : "l"(p));
    return a;
}
__device__ __forceinline__ uint32_t bf16x2(float lo, float hi) {
    uint32_t r; asm("cvt.rn.bf16x2.f32 %0, %1, %2;" : "=r"(r) : "f"(hi), "f"(lo)); return r;
}
__device__ __forceinline__ uint32_t f16x2(float lo, float hi) {
    __half2 h = __floats2half2_rn(lo, hi); return *(uint32_t*)&h;
}

// A rows: 256B (128 bf16), 16B chunks XOR-swizzled by row%8.
__device__ __forceinline__ uint32_t swzA(int row, int kchunk) {
    return (uint32_t)(row * 256 + (((kchunk ^ row) & 7) | (kchunk & 8)) * 16);
}
// B image: k-major, 128 rows x 512B. chunk cn = n/8, swizzled cn ^ (k&7).
__device__ __forceinline__ uint32_t swzB(int k, int cn) {
    return (uint32_t)(k * 512 + ((cn ^ (k & 7)) * 16));
}

// smem layout (bytes)
#define SM_B1    0                        // 512B
#define SM_A0    1024                     // 16 KB
#define SM_A1    (1024 + 16384)           // 16 KB
#define SM_B     (1024 + 32768)           // 64 KB
#define SM_STAGE (SM_B + 65536)           // 64 x 528B = 33792
#define SMEM_BYTES (SM_STAGE + 64 * 528)  // 133120

// ---------------------------------------------------------------------------
// Phase 1: persistent double-buffered HMMA GEMM + PDL trigger.
// ---------------------------------------------------------------------------
__global__ __launch_bounds__(512, 1)
void gemm_mma_kernel(const float* __restrict__ X, const float* __restrict__ W1,
                     const float* __restrict__ b1, int n_nodes, int ntiles)
{
    extern __shared__ unsigned char smem[];
    const uint32_t sb = smem_u32(smem);
    const int tid  = threadIdx.x;
    const int lane = tid & 31;
    const int wid  = tid >> 5;

    if (tid < 128) *(float*)(smem + SM_B1 + tid * 4) = __ldg(b1 + tid);

    // Build k-major bf16 B image (coalesced loads, conflict-free stores).
    #pragma unroll
    for (int i = 0; i < 8; ++i) {
        int id = tid + i * 512;
        int k  = id >> 5;
        int cn = id & 31;
        int n0 = cn * 8;
        const float* src = (n0 < 128) ? W1 + (size_t)k * 128 + n0
                                      : W1 + (size_t)(128 + k) * 128 + (n0 - 128);
        float4 v0 = __ldg((const float4*)src);
        float4 v1 = __ldg((const float4*)src + 1);
        uint4 p;
        p.x = bf16x2(v0.x, v0.y); p.y = bf16x2(v0.z, v0.w);
        p.z = bf16x2(v1.x, v1.y); p.w = bf16x2(v1.z, v1.w);
        *(uint4*)(smem + SM_B + swzB(k, cn)) = p;
    }

    // Let the edge kernel launch early (it pre-loads indices/W2, then waits).
    cudaTriggerProgrammaticLaunchCompletion();

    int tile = blockIdx.x;

    float4 xv[4];
    // load X(tile0)
    {
        int m0 = tile * 64;
        #pragma unroll
        for (int c = 0; c < 4; ++c) {
            int i  = tid + c * 512;
            int m  = i >> 5;
            int k4 = (i & 31) << 2;
            xv[c] = make_float4(0.f, 0.f, 0.f, 0.f);
            if (tile < ntiles && m0 + m < n_nodes)
                xv[c] = __ldg((const float4*)(X + (size_t)(m0 + m) * DK + k4));
        }
    }
    // convert tile0 -> buf0
    #pragma unroll
    for (int c = 0; c < 4; ++c) {
        int i  = tid + c * 512;
        int m  = i >> 5;
        int k4 = (i & 31) << 2;
        *(uint2*)(smem + SM_A0 + swzA(m, k4 >> 3) + (k4 & 7) * 2) =
            make_uint2(bf16x2(xv[c].x, xv[c].y), bf16x2(xv[c].z, xv[c].w));
    }
    // load X(tile1)
    {
        int t1 = tile + NCTAS;
        int m0 = t1 * 64;
        #pragma unroll
        for (int c = 0; c < 4; ++c) {
            int i  = tid + c * 512;
            int m  = i >> 5;
            int k4 = (i & 31) << 2;
            float4 v = make_float4(0.f, 0.f, 0.f, 0.f);
            if (t1 < ntiles && m0 + m < n_nodes)
                v = __ldg((const float4*)(X + (size_t)(m0 + m) * DK + k4));
            xv[c] = v;
        }
    }
    __syncthreads();

    const int wm = wid & 3;
    const int wn = wid >> 2;
    const int a_row   = wm * 16 + ((lane >> 3) & 1) * 8 + (lane & 7);
    const int a_koff  = lane >> 4;
    const int bg      = lane >> 3;
    const int bk_off  = (bg & 1) * 8 + (lane & 7);
    const int bn_off  = (bg >> 1) * 8;
    const int mA = wm * 16 + (lane >> 2);
    const int cq = (lane & 3) * 2;

    int cur = 0;
    while (tile < ntiles) {
        const int m0 = tile * 64;
        const uint32_t bufN = cur ? SM_A0 : SM_A1;   // next buffer (t+1)
        const uint32_t bufC = cur ? SM_A1 : SM_A0;   // current (t)

        // convert(t+1) -> other buffer (independent of mainloop(t) reads)
        #pragma unroll
        for (int c = 0; c < 4; ++c) {
            int i  = tid + c * 512;
            int m  = i >> 5;
            int k4 = (i & 31) << 2;
            *(uint2*)(smem + bufN + swzA(m, k4 >> 3) + (k4 & 7) * 2) =
                make_uint2(bf16x2(xv[c].x, xv[c].y), bf16x2(xv[c].z, xv[c].w));
        }
        // prefetch X(t+2)
        {
            int t2 = tile + 2 * NCTAS;
            int nm0 = t2 * 64;
            #pragma unroll
            for (int c = 0; c < 4; ++c) {
                int i  = tid + c * 512;
                int m  = i >> 5;
                int k4 = (i & 31) << 2;
                float4 v = make_float4(0.f, 0.f, 0.f, 0.f);
                if (t2 < ntiles && nm0 + m < n_nodes)
                    v = __ldg((const float4*)(X + (size_t)(nm0 + m) * DK + k4));
                xv[c] = v;
            }
        }

        // Mainloop on buf(t): frag loads up front per k-step, then 8 MMAs.
        float acc[8][4];
        #pragma unroll
        for (int nb = 0; nb < 8; ++nb)
            #pragma unroll
            for (int j = 0; j < 4; ++j) acc[nb][j] = 0.f;

        #pragma unroll 1
        for (int ks = 0; ks < 8; ++ks) {
            uint32_t a0, a1, a2, a3;
            uint32_t aaddr = sb + bufC + swzA(a_row, ks * 2 + a_koff);
            asm volatile("ldmatrix.sync.aligned.m8n8.x4.shared.b16 {%0,%1,%2,%3}, [%4];"
                         : "=r"(a0), "=r"(a1), "=r"(a2), "=r"(a3) : "r"(aaddr));
            const int kk = ks * 16 + bk_off;
            uint32_t bf[4][4];
            #pragma unroll
            for (int nq = 0; nq < 4; ++nq) {
                int nn = wn * 64 + nq * 16 + bn_off;
                uint32_t baddr = sb + SM_B + swzB(kk, nn >> 3);
                asm volatile("ldmatrix.sync.aligned.m8n8.x4.trans.shared.b16 {%0,%1,%2,%3}, [%4];"
                             : "=r"(bf[nq][0]), "=r"(bf[nq][1]), "=r"(bf[nq][2]), "=r"(bf[nq][3])
                             : "r"(baddr));
            }
            #pragma unroll
            for (int nq = 0; nq < 4; ++nq) {
                asm volatile(
                    "mma.sync.aligned.m16n8k16.row.col.f32.bf16.bf16.f32 "
                    "{%0,%1,%2,%3}, {%4,%5,%6,%7}, {%8,%9}, {%0,%1,%2,%3};"
                    : "+f"(acc[2*nq][0]), "+f"(acc[2*nq][1]), "+f"(acc[2*nq][2]), "+f"(acc[2*nq][3])
                    : "r"(a0), "r"(a1), "r"(a2), "r"(a3), "r"(bf[nq][0]), "r"(bf[nq][1]));
                asm volatile(
                    "mma.sync.aligned.m16n8k16.row.col.f32.bf16.bf16.f32 "
                    "{%0,%1,%2,%3}, {%4,%5,%6,%7}, {%8,%9}, {%0,%1,%2,%3};"
                    : "+f"(acc[2*nq+1][0]), "+f"(acc[2*nq+1][1]), "+f"(acc[2*nq+1][2]), "+f"(acc[2*nq+1][3])
                    : "r"(a0), "r"(a1), "r"(a2), "r"(a3), "r"(bf[nq][2]), "r"(bf[nq][3]));
            }
        }
        __syncthreads();   // mainloop(t) done; STAGE free (STG(t-1) passed); buf reuse safe

        // Epilogue: +b1 on cols<128, fp16 pack, conflict-free staging.
        #pragma unroll
        for (int nb = 0; nb < 8; ++nb) {
            int c = wn * 64 + nb * 8 + cq;
            float add0 = 0.f, add1 = 0.f;
            if (c < 128) {
                float2 bb = *(const float2*)(smem + SM_B1 + c * 4);
                add0 = bb.x; add1 = bb.y;
            }
            uint32_t lo = f16x2(acc[nb][0] + add0, acc[nb][1] + add1);
            uint32_t hi = f16x2(acc[nb][2] + add0, acc[nb][3] + add1);
            *(uint32_t*)(smem + SM_STAGE + mA * 528 + c * 2)       = lo;
            *(uint32_t*)(smem + SM_STAGE + (mA + 8) * 528 + c * 2) = hi;
        }
        __syncthreads();

        // Coalesced STG: 64 rows x 512B.
        uint4* out4 = (uint4*)(g_ABh) + (size_t)m0 * 32;
        #pragma unroll
        for (int t = 0; t < 4; ++t) {
            int i   = tid + t * 512;
            int row = i >> 5;
            int c4  = i & 31;
            if (m0 + row < n_nodes)
                out4[(size_t)row * 32 + c4] =
                    *(const uint4*)(smem + SM_STAGE + row * 528 + c4 * 16);
        }
        tile += NCTAS;
        cur ^= 1;
    }
}

// ---------------------------------------------------------------------------
// Phase 2: half-warp per edge. PDL: prologue (W2/idx loads) overlaps gemm
// tail; cudaGridDependencySynchronize() before touching g_ABh.
// ---------------------------------------------------------------------------
__global__ __launch_bounds__(256, 6)
void edge_kernel(const int* __restrict__ eidx,
                 const float* __restrict__ W2,
                 const float* __restrict__ b2,
                 float* __restrict__ out, int n_edges, int n_nodes)
{
    __shared__ float sres[8][32];

    const int lane = threadIdx.x & 31;
    const int wid  = threadIdx.x >> 5;
    const int base = (blockIdx.x * 8 + wid) * 32;
    if (base >= n_edges) { cudaGridDependencySynchronize(); return; }

    const int hl = lane & 15;
    const int hw = lane >> 4;

    // --- gemm-independent prologue (overlaps primary kernel) ---
    float wd[8];
    #pragma unroll
    for (int t = 0; t < 4; ++t) {
        float4 w = __ldg(((const float4*)W2) + hl * 4 + t);
        wd[2*t]   = w.x - w.y;
        wd[2*t+1] = w.z - w.w;
    }
    const float b2d = __ldg(b2 + 0) - __ldg(b2 + 1);

    int el = base + lane;
    bool valid = el < n_edges;
    int si = valid ? __ldg(eidx + el) : 0;
    int di = valid ? __ldg(eidx + n_edges + el) : 0;
    si = min(max(si, 0), n_nodes - 1);
    di = min(max(di, 0), n_nodes - 1);

    // --- wait for gemm output visibility ---
    cudaGridDependencySynchronize();

    const __half2 z2 = __float2half2_rn(0.f);

    #pragma unroll 4
    for (int i = 0; i < 16; ++i) {
        int s = __shfl_sync(0xffffffffu, si, 2 * i + hw);
        int d = __shfl_sync(0xffffffffu, di, 2 * i + hw);

        uint4 av = __ldg(((const uint4*)(g_ABh + (size_t)s * 256)) + hl);
        uint4 bv = __ldg(((const uint4*)(g_ABh + (size_t)d * 256 + 128)) + hl);

        __half2 h0 = __hmax2(__hadd2(*(__half2*)&av.x, *(__half2*)&bv.x), z2);
        __half2 h1 = __hmax2(__hadd2(*(__half2*)&av.y, *(__half2*)&bv.y), z2);
        __half2 h2 = __hmax2(__hadd2(*(__half2*)&av.z, *(__half2*)&bv.z), z2);
        __half2 h3 = __hmax2(__hadd2(*(__half2*)&av.w, *(__half2*)&bv.w), z2);

        float2 f0 = __half22float2(h0);
        float2 f1 = __half22float2(h1);
        float2 f2 = __half22float2(h2);
        float2 f3 = __half22float2(h3);

        float dlt = f0.x * wd[0];
        dlt = fmaf(f0.y, wd[1], dlt);
        dlt = fmaf(f1.x, wd[2], dlt);
        dlt = fmaf(f1.y, wd[3], dlt);
        dlt = fmaf(f2.x, wd[4], dlt);
        dlt = fmaf(f2.y, wd[5], dlt);
        dlt = fmaf(f3.x, wd[6], dlt);
        dlt = fmaf(f3.y, wd[7], dlt);

        #pragma unroll
        for (int o = 8; o; o >>= 1)
            dlt += __shfl_xor_sync(0xffffffffu, dlt, o);

        if (hl == 0) sres[wid][2 * i + hw] = dlt;
    }
    __syncwarp();

    if (valid) {
        float d0 = sres[wid][lane] + b2d;     // = s0 - s1
        float e  = __expf(-d0);
        float c  = 1.f / (1.f + e);
        out[el]           = c;
        out[n_edges + el] = e * c;
    }
}

extern "C" void kernel_launch(void* const* d_in, const int* in_sizes, int n_in,
                              void* d_out, int out_size)
{
    const float* X    = (const float*)d_in[0];
    const int*   eidx = (const int*)d_in[1];     // int32 on device
    const float* W1   = (const float*)d_in[2];
    const float* b1   = (const float*)d_in[3];
    const float* W2   = (const float*)d_in[4];
    const float* b2   = (const float*)d_in[5];
    float* out = (float*)d_out;

    const int n_nodes = in_sizes[0] / DK;   // 100000
    const int n_edges = in_sizes[1] / 2;    // 640000
    const int ntiles  = (n_nodes + 63) / 64;

    cudaFuncSetAttribute(gemm_mma_kernel, cudaFuncAttributeMaxDynamicSharedMemorySize, SMEM_BYTES);
    gemm_mma_kernel<<<NCTAS, 512, SMEM_BYTES>>>(X, W1, b1, n_nodes, ntiles);

    // Edge kernel with programmatic dependent launch.
    {
        cudaLaunchConfig_t cfg = {};
        cfg.gridDim  = dim3((n_edges + 255) / 256, 1, 1);
        cfg.blockDim = dim3(256, 1, 1);
        cfg.dynamicSmemBytes = 0;
        cudaLaunchAttribute attr[1];
        attr[0].id = cudaLaunchAttributeProgrammaticStreamSerialization;
        attr[0].val.programmaticStreamSerializationAllowed = 1;
        cfg.attrs = attr;
        cfg.numAttrs = 1;
        cudaLaunchKernelEx(&cfg, edge_kernel, eidx, W2, b2, out, n_edges, n_nodes);
    }
}

// round 16
// speedup vs baseline: 1.0293x; 1.0293x over previous
#include <cuda_runtime.h>
#include <cuda_fp16.h>
#include <cstdint>

#define DK 128
#define NCTAS 148

// -------- device-global scratch --------
__device__ __align__(128) __half g_ABh[100000 * 256]; // fp16 [node][ A'(=A+b1) | B ]

__device__ __forceinline__ uint32_t smem_u32(const void* p) {
    uint32_t a; asm("{ .reg .u64 t; cvta.to.shared.u64 t, %1; cvt.u32.u64 %0, t; }" : "=r"(a) : "l"(p));
    return a;
}
__device__ __forceinline__ uint32_t f16x2(float lo, float hi) {
    __half2 h = __floats2half2_rn(lo, hi); return *(uint32_t*)&h;
}

// A rows: 256B (128 fp16), 16B chunks XOR-swizzled by row%8.
__device__ __forceinline__ uint32_t swzA(int row, int kchunk) {
    return (uint32_t)(row * 256 + (((kchunk ^ row) & 7) | (kchunk & 8)) * 16);
}
// B image: k-major, 128 rows x 512B. chunk cn = n/8, swizzled cn ^ (k&7).
__device__ __forceinline__ uint32_t swzB(int k, int cn) {
    return (uint32_t)(k * 512 + ((cn ^ (k & 7)) * 16));
}

// smem layout (bytes)
#define SM_B1    0                       // 256B: b1 as 64 half2 pairs
#define SM_A     1024                    // 16 KB: 64 x 128 fp16 swizzled
#define SM_B     (1024 + 16384)          // 64 KB: 128 k-rows x 512B
#define SM_STAGE (SM_B + 65536)          // 33 KB: 64 rows x 528B
#define SMEM_BYTES (SM_STAGE + 64 * 528) // 116736 -> 1 CTA/SM

// ---------------------------------------------------------------------------
// Phase 1: persistent HMMA GEMM, full fp16 pipeline (fp16 in, fp16 acc).
// grid=148, 512 threads, M-tile 64. (R14 structure, datatype change only.)
// ---------------------------------------------------------------------------
__global__ __launch_bounds__(512, 1)
void gemm_mma_kernel(const float* __restrict__ X, const float* __restrict__ W1,
                     const float* __restrict__ b1, int n_nodes, int ntiles)
{
    extern __shared__ unsigned char smem[];
    const uint32_t sb = smem_u32(smem);
    const int tid  = threadIdx.x;
    const int lane = tid & 31;
    const int wid  = tid >> 5;

    // b1 -> smem as half2 pairs (64 x 4B)
    if (tid < 64) {
        float2 b = *(const float2*)(b1 + tid * 2);
        *(uint32_t*)(smem + SM_B1 + tid * 4) = f16x2(b.x, b.y);
    }

    // Build k-major fp16 B image (coalesced loads, conflict-free stores).
    #pragma unroll
    for (int i = 0; i < 8; ++i) {
        int id = tid + i * 512;
        int k  = id >> 5;
        int cn = id & 31;
        int n0 = cn * 8;
        const float* src = (n0 < 128) ? W1 + (size_t)k * 128 + n0
                                      : W1 + (size_t)(128 + k) * 128 + (n0 - 128);
        float4 v0 = __ldg((const float4*)src);
        float4 v1 = __ldg((const float4*)src + 1);
        uint4 p;
        p.x = f16x2(v0.x, v0.y); p.y = f16x2(v0.z, v0.w);
        p.z = f16x2(v1.x, v1.y); p.w = f16x2(v1.z, v1.w);
        *(uint4*)(smem + SM_B + swzB(k, cn)) = p;
    }

    int tile = blockIdx.x;

    // Register prefetch of X tile: 2048 float4 chunks, 4 per thread.
    float4 xv[4];
    {
        int m0 = tile * 64;
        #pragma unroll
        for (int c = 0; c < 4; ++c) {
            int i  = tid + c * 512;
            int m  = i >> 5;
            int k4 = (i & 31) << 2;
            xv[c] = make_float4(0.f, 0.f, 0.f, 0.f);
            if (tile < ntiles && m0 + m < n_nodes)
                xv[c] = __ldg((const float4*)(X + (size_t)(m0 + m) * DK + k4));
        }
    }
    __syncthreads();

    const int wm = wid & 3;
    const int wn = wid >> 2;
    const int a_row   = wm * 16 + ((lane >> 3) & 1) * 8 + (lane & 7);
    const int a_koff  = lane >> 4;
    const int bg      = lane >> 3;
    const int bk_off  = (bg & 1) * 8 + (lane & 7);
    const int bn_off  = (bg >> 1) * 8;
    const int mA = wm * 16 + (lane >> 2);
    const int cq = (lane & 3) * 2;

    while (tile < ntiles) {
        const int m0 = tile * 64;

        // Convert prefetched X -> fp16 swizzled A smem.
        #pragma unroll
        for (int c = 0; c < 4; ++c) {
            int i  = tid + c * 512;
            int m  = i >> 5;
            int k4 = (i & 31) << 2;
            *(uint2*)(smem + SM_A + swzA(m, k4 >> 3) + (k4 & 7) * 2) =
                make_uint2(f16x2(xv[c].x, xv[c].y), f16x2(xv[c].z, xv[c].w));
        }
        __syncthreads();

        // Prefetch next tile's X into registers (hidden under mainloop).
        const int next = tile + NCTAS;
        {
            int nm0 = next * 64;
            #pragma unroll
            for (int c = 0; c < 4; ++c) {
                int i  = tid + c * 512;
                int m  = i >> 5;
                int k4 = (i & 31) << 2;
                float4 v = make_float4(0.f, 0.f, 0.f, 0.f);
                if (next < ntiles && nm0 + m < n_nodes)
                    v = __ldg((const float4*)(X + (size_t)(nm0 + m) * DK + k4));
                xv[c] = v;
            }
        }

        // Mainloop: 8 k-steps x (1 A-ldsm.x4 + 4 B-ldsm.x4.trans + 8 fp16 mma).
        uint32_t acc[8][2];
        #pragma unroll
        for (int nb = 0; nb < 8; ++nb) { acc[nb][0] = 0u; acc[nb][1] = 0u; }

        #pragma unroll 1
        for (int ks = 0; ks < 8; ++ks) {
            uint32_t a0, a1, a2, a3;
            uint32_t aaddr = sb + SM_A + swzA(a_row, ks * 2 + a_koff);
            asm volatile("ldmatrix.sync.aligned.m8n8.x4.shared.b16 {%0,%1,%2,%3}, [%4];"
                         : "=r"(a0), "=r"(a1), "=r"(a2), "=r"(a3) : "r"(aaddr));
            const int kk = ks * 16 + bk_off;
            #pragma unroll
            for (int nq = 0; nq < 4; ++nq) {
                int nn = wn * 64 + nq * 16 + bn_off;
                uint32_t b0, b1r, b2r, b3r;
                uint32_t baddr = sb + SM_B + swzB(kk, nn >> 3);
                asm volatile("ldmatrix.sync.aligned.m8n8.x4.trans.shared.b16 {%0,%1,%2,%3}, [%4];"
                             : "=r"(b0), "=r"(b1r), "=r"(b2r), "=r"(b3r) : "r"(baddr));
                asm volatile(
                    "mma.sync.aligned.m16n8k16.row.col.f16.f16.f16.f16 "
                    "{%0,%1}, {%2,%3,%4,%5}, {%6,%7}, {%0,%1};"
                    : "+r"(acc[2*nq][0]), "+r"(acc[2*nq][1])
                    : "r"(a0), "r"(a1), "r"(a2), "r"(a3), "r"(b0), "r"(b1r));
                asm volatile(
                    "mma.sync.aligned.m16n8k16.row.col.f16.f16.f16.f16 "
                    "{%0,%1}, {%2,%3,%4,%5}, {%6,%7}, {%0,%1};"
                    : "+r"(acc[2*nq+1][0]), "+r"(acc[2*nq+1][1])
                    : "r"(a0), "r"(a1), "r"(a2), "r"(a3), "r"(b2r), "r"(b3r));
            }
        }
        __syncthreads();

        // Epilogue: +b1 (half2) on cols<128; acc already fp16-packed.
        // acc[nb][0] = half2(row mA,   cols c..c+1)
        // acc[nb][1] = half2(row mA+8, cols c..c+1)
        #pragma unroll
        for (int nb = 0; nb < 8; ++nb) {
            int c = wn * 64 + nb * 8 + cq;
            uint32_t lo = acc[nb][0];
            uint32_t hi = acc[nb][1];
            if (c < 128) {
                __half2 bb = *(__half2*)(smem + SM_B1 + c * 2);
                __half2 l2 = __hadd2(*(__half2*)&lo, bb);
                __half2 h2 = __hadd2(*(__half2*)&hi, bb);
                lo = *(uint32_t*)&l2;
                hi = *(uint32_t*)&h2;
            }
            *(uint32_t*)(smem + SM_STAGE + mA * 528 + c * 2)       = lo;
            *(uint32_t*)(smem + SM_STAGE + (mA + 8) * 528 + c * 2) = hi;
        }
        __syncthreads();

        // Coalesced STG: 64 rows x 512B.
        uint4* out4 = (uint4*)(g_ABh) + (size_t)m0 * 32;
        #pragma unroll
        for (int t = 0; t < 4; ++t) {
            int i   = tid + t * 512;
            int row = i >> 5;
            int c4  = i & 31;
            if (m0 + row < n_nodes)
                out4[(size_t)row * 32 + c4] =
                    *(const uint4*)(smem + SM_STAGE + row * 528 + c4 * 16);
        }
        tile = next;
    }
}

// ---------------------------------------------------------------------------
// Phase 2: half-warp per edge (unchanged from R14; 30.3 us).
// ---------------------------------------------------------------------------
__global__ __launch_bounds__(256, 6)
void edge_kernel(const int* __restrict__ eidx,
                 const float* __restrict__ W2,
                 const float* __restrict__ b2,
                 float* __restrict__ out, int n_edges, int n_nodes)
{
    __shared__ float sres[8][32];

    const int lane = threadIdx.x & 31;
    const int wid  = threadIdx.x >> 5;
    const int base = (blockIdx.x * 8 + wid) * 32;
    if (base >= n_edges) return;

    const int hl = lane & 15;
    const int hw = lane >> 4;

    float wd[8];
    #pragma unroll
    for (int t = 0; t < 4; ++t) {
        float4 w = __ldg(((const float4*)W2) + hl * 4 + t);
        wd[2*t]   = w.x - w.y;
        wd[2*t+1] = w.z - w.w;
    }
    const float b2d = __ldg(b2 + 0) - __ldg(b2 + 1);

    int el = base + lane;
    bool valid = el < n_edges;
    int si = valid ? __ldg(eidx + el) : 0;
    int di = valid ? __ldg(eidx + n_edges + el) : 0;
    si = min(max(si, 0), n_nodes - 1);
    di = min(max(di, 0), n_nodes - 1);

    const __half2 z2 = __float2half2_rn(0.f);

    #pragma unroll 4
    for (int i = 0; i < 16; ++i) {
        int s = __shfl_sync(0xffffffffu, si, 2 * i + hw);
        int d = __shfl_sync(0xffffffffu, di, 2 * i + hw);

        uint4 av = __ldg(((const uint4*)(g_ABh + (size_t)s * 256)) + hl);
        uint4 bv = __ldg(((const uint4*)(g_ABh + (size_t)d * 256 + 128)) + hl);

        __half2 h0 = __hmax2(__hadd2(*(__half2*)&av.x, *(__half2*)&bv.x), z2);
        __half2 h1 = __hmax2(__hadd2(*(__half2*)&av.y, *(__half2*)&bv.y), z2);
        __half2 h2 = __hmax2(__hadd2(*(__half2*)&av.z, *(__half2*)&bv.z), z2);
        __half2 h3 = __hmax2(__hadd2(*(__half2*)&av.w, *(__half2*)&bv.w), z2);

        float2 f0 = __half22float2(h0);
        float2 f1 = __half22float2(h1);
        float2 f2 = __half22float2(h2);
        float2 f3 = __half22float2(h3);

        float dlt = f0.x * wd[0];
        dlt = fmaf(f0.y, wd[1], dlt);
        dlt = fmaf(f1.x, wd[2], dlt);
        dlt = fmaf(f1.y, wd[3], dlt);
        dlt = fmaf(f2.x, wd[4], dlt);
        dlt = fmaf(f2.y, wd[5], dlt);
        dlt = fmaf(f3.x, wd[6], dlt);
        dlt = fmaf(f3.y, wd[7], dlt);

        #pragma unroll
        for (int o = 8; o; o >>= 1)
            dlt += __shfl_xor_sync(0xffffffffu, dlt, o);

        if (hl == 0) sres[wid][2 * i + hw] = dlt;
    }
    __syncwarp();

    if (valid) {
        float d0 = sres[wid][lane] + b2d;     // = s0 - s1
        float e  = __expf(-d0);
        float c  = 1.f / (1.f + e);
        out[el]           = c;
        out[n_edges + el] = e * c;
    }
}

extern "C" void kernel_launch(void* const* d_in, const int* in_sizes, int n_in,
                              void* d_out, int out_size)
{
    const float* X    = (const float*)d_in[0];
    const int*   eidx = (const int*)d_in[1];     // int32 on device
    const float* W1   = (const float*)d_in[2];
    const float* b1   = (const float*)d_in[3];
    const float* W2   = (const float*)d_in[4];
    const float* b2   = (const float*)d_in[5];
    float* out = (float*)d_out;

    const int n_nodes = in_sizes[0] / DK;   // 100000
    const int n_edges = in_sizes[1] / 2;    // 640000
    const int ntiles  = (n_nodes + 63) / 64;

    cudaFuncSetAttribute(gemm_mma_kernel, cudaFuncAttributeMaxDynamicSharedMemorySize, SMEM_BYTES);
    gemm_mma_kernel<<<NCTAS, 512, SMEM_BYTES>>>(X, W1, b1, n_nodes, ntiles);

    int edge_blocks = (n_edges + 255) / 256;
    edge_kernel<<<edge_blocks, 256>>>(eidx, W2, b2, out, n_edges, n_nodes);
}